// round 11
// baseline (speedup 1.0000x reference)
#include <cuda_runtime.h>
#include <cstdint>

// GeometricLoss via spatial grid, R11:
//  K1 build (1 CTA): bbox + mean/sigma -> grid over mean±2.5σ (outliers
//     clamp into edge cells -> tail queries terminate in 1-2 rings) ->
//     smem bin count -> shfl prefix scan -> scatter.
//  K2 search: one warp per binned slot. Disk D=1 = flattened union of <=3
//     contiguous row ranges (coalesced). Rings: LANE-PER-CELL (all cellinfo
//     loads parallel). Dirty-gated exact warp merge. Exact ring bound (valid
//     under clamping: unscanned ring >= D+1 -> dist >= D*cellmin).
// Keys (d2_bits<<32)|pid unique & totally ordered -> order-independent exact
// selection, jax.lax.top_k low-index tie-break, deterministic output.

#define NPTS 8192
#define NCH 16
#define KNN 5
#define G 64
#define NCELL (G * G)
#define FULLM 0xFFFFFFFFu
typedef unsigned long long ull;
#define SENT 0xFFFFFFFFFFFFFFFFULL

__device__ float4 g_pts4[NPTS];       // {x, y, bitcast(pid), 0}
__device__ int2   g_cellinfo[NCELL];  // {start, count}
__device__ float  g_partial[NPTS];    // indexed by ORIGINAL pid
__device__ unsigned g_ticket;
__device__ float g_minx, g_miny, g_invw, g_invh, g_cwmin;

// ======================= K1: build (single CTA) =======================
__global__ __launch_bounds__(1024, 1)
void build_kernel(const float2* __restrict__ pts) {
    __shared__ int   s_cnt[NCELL];    // 16 KB
    __shared__ int   s_start[NCELL];  // 16 KB
    __shared__ int   s_wsum[32];
    __shared__ float s_red[128];
    __shared__ float s_stat[128];
    __shared__ float s_minx, s_miny, s_invw, s_invh;

    const int tid = threadIdx.x;
    const int lane = tid & 31, warp = tid >> 5;

#pragma unroll
    for (int i = 0; i < NCELL / 1024; i++) s_cnt[tid + i * 1024] = 0;
    if (tid == 0) g_ticket = 0;

    // ---- bbox + stats ----
    float2 loc[NPTS / 1024];
    float mnx = 1e30f, mxx = -1e30f, mny = 1e30f, mxy = -1e30f;
    float sx = 0.f, sy = 0.f, sxx = 0.f, syy = 0.f;
#pragma unroll
    for (int i = 0; i < NPTS / 1024; i++) {
        float2 p = pts[tid + i * 1024];
        loc[i] = p;
        mnx = fminf(mnx, p.x); mxx = fmaxf(mxx, p.x);
        mny = fminf(mny, p.y); mxy = fmaxf(mxy, p.y);
        sx += p.x; sy += p.y;
        sxx = fmaf(p.x, p.x, sxx); syy = fmaf(p.y, p.y, syy);
    }
#pragma unroll
    for (int off = 16; off > 0; off >>= 1) {
        mnx = fminf(mnx, __shfl_xor_sync(FULLM, mnx, off));
        mxx = fmaxf(mxx, __shfl_xor_sync(FULLM, mxx, off));
        mny = fminf(mny, __shfl_xor_sync(FULLM, mny, off));
        mxy = fmaxf(mxy, __shfl_xor_sync(FULLM, mxy, off));
        sx  += __shfl_xor_sync(FULLM, sx,  off);
        sy  += __shfl_xor_sync(FULLM, sy,  off);
        sxx += __shfl_xor_sync(FULLM, sxx, off);
        syy += __shfl_xor_sync(FULLM, syy, off);
    }
    if (lane == 0) {
        s_red[warp] = mnx; s_red[32 + warp] = mxx;
        s_red[64 + warp] = mny; s_red[96 + warp] = mxy;
        s_stat[warp] = sx; s_stat[32 + warp] = sy;
        s_stat[64 + warp] = sxx; s_stat[96 + warp] = syy;
    }
    __syncthreads();
    if (warp == 0) {
        float a = s_red[lane], bx = s_red[32 + lane];
        float c = s_red[64 + lane], dym = s_red[96 + lane];
        float tx = s_stat[lane], ty = s_stat[32 + lane];
        float txx = s_stat[64 + lane], tyy = s_stat[96 + lane];
#pragma unroll
        for (int off = 16; off > 0; off >>= 1) {
            a   = fminf(a,   __shfl_xor_sync(FULLM, a,   off));
            bx  = fmaxf(bx,  __shfl_xor_sync(FULLM, bx,  off));
            c   = fminf(c,   __shfl_xor_sync(FULLM, c,   off));
            dym = fmaxf(dym, __shfl_xor_sync(FULLM, dym, off));
            tx  += __shfl_xor_sync(FULLM, tx,  off);
            ty  += __shfl_xor_sync(FULLM, ty,  off);
            txx += __shfl_xor_sync(FULLM, txx, off);
            tyy += __shfl_xor_sync(FULLM, tyy, off);
        }
        if (lane == 0) {
            const float invn = 1.0f / (float)NPTS;
            float mx = tx * invn, my = ty * invn;
            float vx = fmaxf(txx * invn - mx * mx, 0.0f);
            float vy = fmaxf(tyy * invn - my * my, 0.0f);
            float sdx = sqrtf(vx), sdy = sqrtf(vy);
            // clamp grid to mean +/- 2.5 sigma (but not beyond the bbox)
            float lox = fmaxf(a,  mx - 2.5f * sdx);
            float hix = fminf(bx, mx + 2.5f * sdx);
            float loy = fmaxf(c,  my - 2.5f * sdy);
            float hiy = fminf(dym, my + 2.5f * sdy);
            if (!(hix > lox)) { lox = a; hix = bx; }
            if (!(hiy > loy)) { loy = c; hiy = dym; }
            float w = hix - lox, h = hiy - loy;
            s_minx = lox; g_minx = lox;
            s_miny = loy; g_miny = loy;
            float iw = (w > 0.0f) ? (float)G / w : 0.0f;
            float ih = (h > 0.0f) ? (float)G / h : 0.0f;
            s_invw = iw; g_invw = iw;
            s_invh = ih; g_invh = ih;
            g_cwmin = fminf(w / (float)G, h / (float)G);
        }
    }
    __syncthreads();

    // ---- count (clamped cell assignment) ----
    int mycell[NPTS / 1024];
#pragma unroll
    for (int i = 0; i < NPTS / 1024; i++) {
        int cx = min(max((int)((loc[i].x - s_minx) * s_invw), 0), G - 1);
        int cy = min(max((int)((loc[i].y - s_miny) * s_invh), 0), G - 1);
        int c = cy * G + cx;
        mycell[i] = c;
        atomicAdd(&s_cnt[c], 1);
    }
    __syncthreads();

    // ---- prefix scan: 4 cells/thread + shfl warp scan + cross-warp scan ----
    int v[4], run = 0;
    const int base = tid * 4;
#pragma unroll
    for (int i = 0; i < 4; i++) { v[i] = run; run += s_cnt[base + i]; }
    int inc = run;
#pragma unroll
    for (int off = 1; off < 32; off <<= 1) {
        int y = __shfl_up_sync(FULLM, inc, off);
        if (lane >= off) inc += y;
    }
    if (lane == 31) s_wsum[warp] = inc;
    __syncthreads();
    if (warp == 0) {
        int x = s_wsum[lane];
#pragma unroll
        for (int off = 1; off < 32; off <<= 1) {
            int y = __shfl_up_sync(FULLM, x, off);
            if (lane >= off) x += y;
        }
        s_wsum[lane] = x;
    }
    __syncthreads();
    int pre = ((warp > 0) ? s_wsum[warp - 1] : 0) + inc - run;
#pragma unroll
    for (int i = 0; i < 4; i++) {
        int st = pre + v[i];
        s_start[base + i] = st;
        g_cellinfo[base + i] = make_int2(st, s_cnt[base + i]);
    }
    __syncthreads();

    // ---- scatter (atomic cursor; downstream is order-independent) ----
#pragma unroll
    for (int i = 0; i < NPTS / 1024; i++) {
        int slot = atomicAdd(&s_start[mycell[i]], 1);
        g_pts4[slot] = make_float4(loc[i].x, loc[i].y,
                                   __int_as_float(tid + i * 1024), 0.0f);
    }
}

// ======================= K2: search (warp per binned slot) =============
#define STPB 256
#define SWPB (STPB / 32)            // 8 warps/CTA
#define SNBLK (NPTS / SWPB)         // 1024 CTAs

// Per-lane sorted top-6 insert (raw d2 bits in high word: d2 >= 0).
__device__ __forceinline__ void ins6(ull* b, float d2, unsigned pid) {
    ull key = ((ull)__float_as_uint(d2) << 32) | pid;
    if (key < b[5]) {
        b[5] = key;
#pragma unroll
        for (int t = 5; t > 0; t--) {
            if (b[t] < b[t - 1]) { ull tmp = b[t]; b[t] = b[t - 1]; b[t - 1] = tmp; }
        }
    }
}

// Exact warp merge: fold previous ranks rk into lane lists, 6 warp-min
// extraction rounds over unique keys -> exact, order-independent.
__device__ __forceinline__ void merge6(ull* b, ull& rk, float& th, int lane) {
    if (lane < 6 && rk != SENT && rk < b[5]) {
        b[5] = rk;
#pragma unroll
        for (int t = 5; t > 0; t--) {
            if (b[t] < b[t - 1]) { ull tmp = b[t]; b[t] = b[t - 1]; b[t - 1] = tmp; }
        }
    }
    ull newrk = SENT;
#pragma unroll
    for (int r = 0; r < 6; r++) {
        ull m = b[0];
#pragma unroll
        for (int off = 16; off > 0; off >>= 1) {
            ull o = __shfl_xor_sync(FULLM, m, off);
            if (o < m) m = o;
        }
        if (lane == r) newrk = m;
        if (b[0] == m && m != SENT) {
            b[0] = b[1]; b[1] = b[2]; b[2] = b[3];
            b[3] = b[4]; b[4] = b[5]; b[5] = SENT;
        }
    }
    rk = newrk;
    ull k5 = __shfl_sync(FULLM, newrk, 5);
    unsigned hi5 = (unsigned)(k5 >> 32);
    th = (hi5 == 0xFFFFFFFFu) ? __int_as_float(0x7F800000)
                              : __uint_as_float(hi5);
}

// Lane-private scan of one cell (parallel across lanes; divergent lengths
// but all cellinfo loads issue in parallel -> short latency chain).
__device__ __forceinline__ bool scan_cell_lane(int x, int y, float qx,
                                               float qy, float th, ull* b) {
    if ((unsigned)x >= G || (unsigned)y >= G) return false;
    int2 ci = g_cellinfo[y * G + x];
    bool dirty = false;
    int e = ci.x + ci.y;
    for (int j = ci.x; j < e; j++) {
        float4 P = g_pts4[j];
        float dx = qx - P.x;
        float dy = qy - P.y;
        float d2 = fmaf(dx, dx, dy * dy);
        if (d2 <= th) {
            ins6(b, d2, (unsigned)__float_as_int(P.z));
            dirty = true;
        }
    }
    return dirty;
}

__global__ __launch_bounds__(STPB)
void search_kernel(const float* __restrict__ outputs,
                   float* __restrict__ out) {
    const int slot = blockIdx.x * SWPB + (threadIdx.x >> 5);
    const int lane = threadIdx.x & 31;

    const float4 Q = g_pts4[slot];      // broadcast load
    const float qx = Q.x, qy = Q.y;
    const unsigned qpid = (unsigned)__float_as_int(Q.z);
    const float cw = g_cwmin;
    const int cx = min(max((int)((qx - g_minx) * g_invw), 0), G - 1);
    const int cy = min(max((int)((qy - g_miny) * g_invh), 0), G - 1);

    ull b[6];
#pragma unroll
    for (int t = 0; t < 6; t++) b[t] = SENT;
    ull rk = SENT;
    float th = __int_as_float(0x7F800000);

    // ---- disk D=1: flattened union of <=3 contiguous row ranges ----
    {
        int xa = max(cx - 1, 0), xb = min(cx + 1, G - 1);
        int ya = max(cy - 1, 0), yb = min(cy + 1, G - 1);
        int s0 = 0, l0 = 0, s1 = 0, l1 = 0, s2 = 0, l2 = 0;
        {
            int2 c0 = g_cellinfo[ya * G + xa];
            int2 c1 = g_cellinfo[ya * G + xb];
            s0 = c0.x; l0 = c1.x + c1.y - c0.x;
        }
        if (ya + 1 <= yb) {
            int2 c0 = g_cellinfo[(ya + 1) * G + xa];
            int2 c1 = g_cellinfo[(ya + 1) * G + xb];
            s1 = c0.x; l1 = c1.x + c1.y - c0.x;
        }
        if (ya + 2 <= yb) {
            int2 c0 = g_cellinfo[(ya + 2) * G + xa];
            int2 c1 = g_cellinfo[(ya + 2) * G + xb];
            s2 = c0.x; l2 = c1.x + c1.y - c0.x;
        }
        int o1 = l0, o2 = l0 + l1, tot = o2 + l2;
        for (int t = lane; t < tot; t += 32) {
            int j;
            if (t < o1)      j = s0 + t;
            else if (t < o2) j = s1 + (t - o1);
            else             j = s2 + (t - o2);
            float4 P = g_pts4[j];
            float dx = qx - P.x;
            float dy = qy - P.y;
            float d2 = fmaf(dx, dx, dy * dy);
            ins6(b, d2, (unsigned)__float_as_int(P.z));
        }
    }
    merge6(b, rk, th, lane);

    // ---- expanding rings: LANE-PER-CELL (parallel loads), gated merge ----
    int D = 1;
    while (D < G) {
        float bnd = (float)D * cw;
        if (th <= bnd * bnd) break;  // unscanned rings >= D+1 -> dist >= D*cw
        const int d = D + 1;
        const int ncells = 8 * d;
        bool dirty = false;
        for (int tb = 0; tb < ncells; tb += 32) {
            int t = tb + lane;
            if (t < ncells) {
                int x, y;
                int rowspan = 2 * d + 1;
                if (t < 2 * rowspan) {
                    int row = t / rowspan, k = t % rowspan;
                    x = cx - d + k;
                    y = row ? cy + d : cy - d;
                } else {
                    int t2 = t - 2 * rowspan;
                    int colspan = 2 * d - 1;
                    int col = t2 / colspan, k = t2 % colspan;
                    x = col ? cx + d : cx - d;
                    y = cy - d + 1 + k;
                }
                dirty |= scan_cell_lane(x, y, qx, qy, th, b);
            }
        }
        if (__ballot_sync(FULLM, dirty)) merge6(b, rk, th, lane);
        D = d;
    }

    // ---- epilogue: rank 0 = self (d2=0 min key); lanes 1..5 = neighbors ----
    {
        float s = 0.0f;
        if (lane >= 1 && lane <= KNN) {
            int nb = (int)(rk & 0xFFFFFFFFULL);
            const float4* oq = (const float4*)(outputs + (size_t)qpid * NCH);
            const float4* on = (const float4*)(outputs + (size_t)nb * NCH);
            float acc = 0.0f;
#pragma unroll
            for (int c = 0; c < NCH / 4; c++) {
                float4 a = oq[c];
                float4 bb = on[c];
                float d;
                d = a.x - bb.x; acc = fmaf(d, d, acc);
                d = a.y - bb.y; acc = fmaf(d, d, acc);
                d = a.z - bb.z; acc = fmaf(d, d, acc);
                d = a.w - bb.w; acc = fmaf(d, d, acc);
            }
            s = sqrtf(acc);
        }
#pragma unroll
        for (int off = 16; off > 0; off >>= 1)
            s += __shfl_xor_sync(FULLM, s, off);
        if (lane == 0) g_partial[qpid] = s;   // pid-indexed: fixed sum order
    }

    // ---- fused final reduction: last CTA does a fixed-order sum ----
    __syncthreads();
    __shared__ bool is_last;
    if (threadIdx.x == 0) {
        __threadfence();
        unsigned tk = atomicAdd(&g_ticket, 1);
        is_last = (tk == SNBLK - 1);
    }
    __syncthreads();
    if (is_last) {
        __threadfence();
        float acc = 0.0f;
        for (int j = threadIdx.x; j < NPTS; j += STPB) acc += g_partial[j];
        __shared__ float sm[STPB];
        sm[threadIdx.x] = acc;
        __syncthreads();
        for (int st = STPB / 2; st > 0; st >>= 1) {
            if (threadIdx.x < st) sm[threadIdx.x] += sm[threadIdx.x + st];
            __syncthreads();
        }
        if (threadIdx.x == 0) {
            out[0] = sm[0] / (float)(NPTS * KNN);
            g_ticket = 0;  // reset for next graph replay
        }
    }
}

extern "C" void kernel_launch(void* const* d_in, const int* in_sizes, int n_in,
                              void* d_out, int out_size) {
    const float*  outputs = (const float*)d_in[0];
    const float2* points  = (const float2*)d_in[1];
    float* out = (float*)d_out;

    build_kernel<<<1, 1024>>>(points);
    search_kernel<<<SNBLK, STPB>>>(outputs, out);
}

// round 12
// speedup vs baseline: 1.2814x; 1.2814x over previous
#include <cuda_runtime.h>
#include <cstdint>

// GeometricLoss via spatial grid, R12: all grid data in SMEM.
//  K1 build (1 CTA): bbox + mean/sigma -> 48x48 grid over mean±2.5σ (clamped)
//     -> smem count -> shfl prefix scan -> scatter g_pts4 + g_cellinfo.
//  K2 search: 148 persistent CTAs (1/SM, single wave). Each CTA caches ALL
//     points (128KB) + cell table (18KB) in smem; warps grid-stride over
//     queries. Disk D=1 flattened rows (LDS.128), per-lane top-6, exact warp
//     merge, exact ring bound (rings rare at G=48, served from smem).
// Keys (d2_bits<<32)|pid unique & totally ordered -> order-independent exact
// selection, jax.lax.top_k low-index tie-break, deterministic output.

#define NPTS 8192
#define NCH 16
#define KNN 5
#define G 48
#define NCELL (G * G)          // 2304
#define NCELL_PAD 3072         // 3 cells/thread in build scan
#define FULLM 0xFFFFFFFFu
typedef unsigned long long ull;
#define SENT 0xFFFFFFFFFFFFFFFFULL

__device__ float4 g_pts4[NPTS];       // {x, y, bitcast(pid), 0}
__device__ int2   g_cellinfo[NCELL];  // {start, count}
__device__ float  g_partial[NPTS];    // indexed by ORIGINAL pid
__device__ unsigned g_ticket;
__device__ float g_minx, g_miny, g_invw, g_invh, g_cwmin;

// ======================= K1: build (single CTA) =======================
__global__ __launch_bounds__(1024, 1)
void build_kernel(const float2* __restrict__ pts) {
    __shared__ int   s_cnt[NCELL_PAD];
    __shared__ int   s_start[NCELL_PAD];
    __shared__ int   s_wsum[32];
    __shared__ float s_red[128];
    __shared__ float s_stat[128];
    __shared__ float s_minx, s_miny, s_invw, s_invh;

    const int tid = threadIdx.x;
    const int lane = tid & 31, warp = tid >> 5;

#pragma unroll
    for (int i = 0; i < NCELL_PAD / 1024; i++) s_cnt[tid + i * 1024] = 0;
    if (tid == 0) g_ticket = 0;

    // ---- bbox + mean/var ----
    float2 loc[NPTS / 1024];
    float mnx = 1e30f, mxx = -1e30f, mny = 1e30f, mxy = -1e30f;
    float sx = 0.f, sy = 0.f, sxx = 0.f, syy = 0.f;
#pragma unroll
    for (int i = 0; i < NPTS / 1024; i++) {
        float2 p = pts[tid + i * 1024];
        loc[i] = p;
        mnx = fminf(mnx, p.x); mxx = fmaxf(mxx, p.x);
        mny = fminf(mny, p.y); mxy = fmaxf(mxy, p.y);
        sx += p.x; sy += p.y;
        sxx = fmaf(p.x, p.x, sxx); syy = fmaf(p.y, p.y, syy);
    }
#pragma unroll
    for (int off = 16; off > 0; off >>= 1) {
        mnx = fminf(mnx, __shfl_xor_sync(FULLM, mnx, off));
        mxx = fmaxf(mxx, __shfl_xor_sync(FULLM, mxx, off));
        mny = fminf(mny, __shfl_xor_sync(FULLM, mny, off));
        mxy = fmaxf(mxy, __shfl_xor_sync(FULLM, mxy, off));
        sx  += __shfl_xor_sync(FULLM, sx,  off);
        sy  += __shfl_xor_sync(FULLM, sy,  off);
        sxx += __shfl_xor_sync(FULLM, sxx, off);
        syy += __shfl_xor_sync(FULLM, syy, off);
    }
    if (lane == 0) {
        s_red[warp] = mnx; s_red[32 + warp] = mxx;
        s_red[64 + warp] = mny; s_red[96 + warp] = mxy;
        s_stat[warp] = sx; s_stat[32 + warp] = sy;
        s_stat[64 + warp] = sxx; s_stat[96 + warp] = syy;
    }
    __syncthreads();
    if (warp == 0) {
        float a = s_red[lane], bx = s_red[32 + lane];
        float c = s_red[64 + lane], dym = s_red[96 + lane];
        float tx = s_stat[lane], ty = s_stat[32 + lane];
        float txx = s_stat[64 + lane], tyy = s_stat[96 + lane];
#pragma unroll
        for (int off = 16; off > 0; off >>= 1) {
            a   = fminf(a,   __shfl_xor_sync(FULLM, a,   off));
            bx  = fmaxf(bx,  __shfl_xor_sync(FULLM, bx,  off));
            c   = fminf(c,   __shfl_xor_sync(FULLM, c,   off));
            dym = fmaxf(dym, __shfl_xor_sync(FULLM, dym, off));
            tx  += __shfl_xor_sync(FULLM, tx,  off);
            ty  += __shfl_xor_sync(FULLM, ty,  off);
            txx += __shfl_xor_sync(FULLM, txx, off);
            tyy += __shfl_xor_sync(FULLM, tyy, off);
        }
        if (lane == 0) {
            const float invn = 1.0f / (float)NPTS;
            float mx = tx * invn, my = ty * invn;
            float vx = fmaxf(txx * invn - mx * mx, 0.0f);
            float vy = fmaxf(tyy * invn - my * my, 0.0f);
            float sdx = sqrtf(vx), sdy = sqrtf(vy);
            float lox = fmaxf(a,   mx - 2.5f * sdx);
            float hix = fminf(bx,  mx + 2.5f * sdx);
            float loy = fmaxf(c,   my - 2.5f * sdy);
            float hiy = fminf(dym, my + 2.5f * sdy);
            if (!(hix > lox)) { lox = a; hix = bx; }
            if (!(hiy > loy)) { loy = c; hiy = dym; }
            float w = hix - lox, h = hiy - loy;
            s_minx = lox; g_minx = lox;
            s_miny = loy; g_miny = loy;
            float iw = (w > 0.0f) ? (float)G / w : 0.0f;
            float ih = (h > 0.0f) ? (float)G / h : 0.0f;
            s_invw = iw; g_invw = iw;
            s_invh = ih; g_invh = ih;
            g_cwmin = fminf(w / (float)G, h / (float)G);
        }
    }
    __syncthreads();

    // ---- count (clamped cell assignment) ----
    int mycell[NPTS / 1024];
#pragma unroll
    for (int i = 0; i < NPTS / 1024; i++) {
        int cx = min(max((int)((loc[i].x - s_minx) * s_invw), 0), G - 1);
        int cy = min(max((int)((loc[i].y - s_miny) * s_invh), 0), G - 1);
        int c = cy * G + cx;
        mycell[i] = c;
        atomicAdd(&s_cnt[c], 1);
    }
    __syncthreads();

    // ---- prefix scan: 3 cells/thread + shfl warp scan + cross-warp scan ----
    int v[3], run = 0;
    const int base = tid * 3;
#pragma unroll
    for (int i = 0; i < 3; i++) { v[i] = run; run += s_cnt[base + i]; }
    int inc = run;
#pragma unroll
    for (int off = 1; off < 32; off <<= 1) {
        int y = __shfl_up_sync(FULLM, inc, off);
        if (lane >= off) inc += y;
    }
    if (lane == 31) s_wsum[warp] = inc;
    __syncthreads();
    if (warp == 0) {
        int x = s_wsum[lane];
#pragma unroll
        for (int off = 1; off < 32; off <<= 1) {
            int y = __shfl_up_sync(FULLM, x, off);
            if (lane >= off) x += y;
        }
        s_wsum[lane] = x;
    }
    __syncthreads();
    int pre = ((warp > 0) ? s_wsum[warp - 1] : 0) + inc - run;
#pragma unroll
    for (int i = 0; i < 3; i++) {
        int st = pre + v[i];
        s_start[base + i] = st;
        if (base + i < NCELL)
            g_cellinfo[base + i] = make_int2(st, s_cnt[base + i]);
    }
    __syncthreads();

    // ---- scatter (atomic cursor; downstream is order-independent) ----
#pragma unroll
    for (int i = 0; i < NPTS / 1024; i++) {
        int slot = atomicAdd(&s_start[mycell[i]], 1);
        g_pts4[slot] = make_float4(loc[i].x, loc[i].y,
                                   __int_as_float(tid + i * 1024), 0.0f);
    }
}

// ======================= K2: search (persistent, all-smem) =============
#define STPB 1024
#define SNBLK 148
#define NWARPS (SNBLK * (STPB / 32))   // 4736

extern __shared__ char smem_dyn[];     // float4[NPTS] + int2[NCELL]

// Per-lane sorted top-6 insert.
__device__ __forceinline__ void ins6(ull* b, float d2, unsigned pid) {
    ull key = ((ull)__float_as_uint(d2) << 32) | pid;
    if (key < b[5]) {
        b[5] = key;
#pragma unroll
        for (int t = 5; t > 0; t--) {
            if (b[t] < b[t - 1]) { ull tmp = b[t]; b[t] = b[t - 1]; b[t - 1] = tmp; }
        }
    }
}

// Exact warp merge over unique keys.
__device__ __forceinline__ void merge6(ull* b, ull& rk, float& th, int lane) {
    if (lane < 6 && rk != SENT && rk < b[5]) {
        b[5] = rk;
#pragma unroll
        for (int t = 5; t > 0; t--) {
            if (b[t] < b[t - 1]) { ull tmp = b[t]; b[t] = b[t - 1]; b[t - 1] = tmp; }
        }
    }
    ull newrk = SENT;
#pragma unroll
    for (int r = 0; r < 6; r++) {
        ull m = b[0];
#pragma unroll
        for (int off = 16; off > 0; off >>= 1) {
            ull o = __shfl_xor_sync(FULLM, m, off);
            if (o < m) m = o;
        }
        if (lane == r) newrk = m;
        if (b[0] == m && m != SENT) {
            b[0] = b[1]; b[1] = b[2]; b[2] = b[3];
            b[3] = b[4]; b[4] = b[5]; b[5] = SENT;
        }
    }
    rk = newrk;
    ull k5 = __shfl_sync(FULLM, newrk, 5);
    unsigned hi5 = (unsigned)(k5 >> 32);
    th = (hi5 == 0xFFFFFFFFu) ? __int_as_float(0x7F800000)
                              : __uint_as_float(hi5);
}

__global__ __launch_bounds__(STPB, 1)
void search_kernel(const float* __restrict__ outputs,
                   float* __restrict__ out) {
    float4* s_pts  = (float4*)smem_dyn;
    int2*   s_cell = (int2*)(smem_dyn + NPTS * sizeof(float4));

    const int tid = threadIdx.x;
    const int lane = tid & 31;
    const int gwarp = blockIdx.x * (STPB / 32) + (tid >> 5);

    // ---- cache everything in smem ----
    for (int i = tid; i < NPTS; i += STPB) s_pts[i] = g_pts4[i];
    for (int i = tid; i < NCELL; i += STPB) s_cell[i] = g_cellinfo[i];
    __syncthreads();

    const float minx = g_minx, miny = g_miny;
    const float invw = g_invw, invh = g_invh;
    const float cw = g_cwmin;

    // ---- warps grid-stride over queries (binned slot order) ----
    for (int q = gwarp; q < NPTS; q += NWARPS) {
        const float4 Q = s_pts[q];
        const float qx = Q.x, qy = Q.y;
        const unsigned qpid = (unsigned)__float_as_int(Q.z);
        const int cx = min(max((int)((qx - minx) * invw), 0), G - 1);
        const int cy = min(max((int)((qy - miny) * invh), 0), G - 1);

        ull b[6];
#pragma unroll
        for (int t = 0; t < 6; t++) b[t] = SENT;
        ull rk = SENT;
        float th = __int_as_float(0x7F800000);

        // disk D=1: flattened union of <=3 contiguous row ranges (smem)
        {
            int xa = max(cx - 1, 0), xb = min(cx + 1, G - 1);
            int ya = max(cy - 1, 0), yb = min(cy + 1, G - 1);
            int s0 = 0, l0 = 0, s1 = 0, l1 = 0, s2 = 0, l2 = 0;
            {
                int2 c0 = s_cell[ya * G + xa];
                int2 c1 = s_cell[ya * G + xb];
                s0 = c0.x; l0 = c1.x + c1.y - c0.x;
            }
            if (ya + 1 <= yb) {
                int2 c0 = s_cell[(ya + 1) * G + xa];
                int2 c1 = s_cell[(ya + 1) * G + xb];
                s1 = c0.x; l1 = c1.x + c1.y - c0.x;
            }
            if (ya + 2 <= yb) {
                int2 c0 = s_cell[(ya + 2) * G + xa];
                int2 c1 = s_cell[(ya + 2) * G + xb];
                s2 = c0.x; l2 = c1.x + c1.y - c0.x;
            }
            int o1 = l0, o2 = l0 + l1, tot = o2 + l2;
            for (int t = lane; t < tot; t += 32) {
                int j;
                if (t < o1)      j = s0 + t;
                else if (t < o2) j = s1 + (t - o1);
                else             j = s2 + (t - o2);
                float4 P = s_pts[j];
                float dx = qx - P.x;
                float dy = qy - P.y;
                float d2 = fmaf(dx, dx, dy * dy);
                ins6(b, d2, (unsigned)__float_as_int(P.z));
            }
        }
        merge6(b, rk, th, lane);

        // expanding rings from smem (rare at G=48), lane-per-cell
        int D = 1;
        while (D < G) {
            float bnd = (float)D * cw;
            if (th <= bnd * bnd) break;
            const int d = D + 1;
            const int ncells = 8 * d;
            bool dirty = false;
            for (int tb = 0; tb < ncells; tb += 32) {
                int t = tb + lane;
                if (t < ncells) {
                    int x, y;
                    int rowspan = 2 * d + 1;
                    if (t < 2 * rowspan) {
                        int row = t / rowspan, k = t % rowspan;
                        x = cx - d + k;
                        y = row ? cy + d : cy - d;
                    } else {
                        int t2 = t - 2 * rowspan;
                        int colspan = 2 * d - 1;
                        int col = t2 / colspan, k = t2 % colspan;
                        x = col ? cx + d : cx - d;
                        y = cy - d + 1 + k;
                    }
                    if ((unsigned)x < G && (unsigned)y < G) {
                        int2 ci = s_cell[y * G + x];
                        int e = ci.x + ci.y;
                        for (int j = ci.x; j < e; j++) {
                            float4 P = s_pts[j];
                            float dx = qx - P.x;
                            float dy = qy - P.y;
                            float d2 = fmaf(dx, dx, dy * dy);
                            if (d2 <= th) {
                                ins6(b, d2, (unsigned)__float_as_int(P.z));
                                dirty = true;
                            }
                        }
                    }
                }
            }
            if (__ballot_sync(FULLM, dirty)) merge6(b, rk, th, lane);
            D = d;
        }

        // epilogue: rank 0 = self; lanes 1..5 own the neighbor keys
        {
            float s = 0.0f;
            if (lane >= 1 && lane <= KNN) {
                int nb = (int)(rk & 0xFFFFFFFFULL);
                const float4* oq = (const float4*)(outputs + (size_t)qpid * NCH);
                const float4* on = (const float4*)(outputs + (size_t)nb * NCH);
                float acc = 0.0f;
#pragma unroll
                for (int c = 0; c < NCH / 4; c++) {
                    float4 a = oq[c];
                    float4 bb = on[c];
                    float d;
                    d = a.x - bb.x; acc = fmaf(d, d, acc);
                    d = a.y - bb.y; acc = fmaf(d, d, acc);
                    d = a.z - bb.z; acc = fmaf(d, d, acc);
                    d = a.w - bb.w; acc = fmaf(d, d, acc);
                }
                s = sqrtf(acc);
            }
#pragma unroll
            for (int off = 16; off > 0; off >>= 1)
                s += __shfl_xor_sync(FULLM, s, off);
            if (lane == 0) g_partial[qpid] = s;
        }
    }

    // ---- fused final reduction: last CTA does a fixed-order sum ----
    __syncthreads();
    __shared__ bool is_last;
    if (tid == 0) {
        __threadfence();
        unsigned tk = atomicAdd(&g_ticket, 1);
        is_last = (tk == SNBLK - 1);
    }
    __syncthreads();
    if (is_last) {
        __threadfence();
        float acc = 0.0f;
        for (int j = tid; j < NPTS; j += STPB) acc += g_partial[j];
        __shared__ float sm[STPB];
        sm[tid] = acc;
        __syncthreads();
        for (int st = STPB / 2; st > 0; st >>= 1) {
            if (tid < st) sm[tid] += sm[tid + st];
            __syncthreads();
        }
        if (tid == 0) {
            out[0] = sm[0] / (float)(NPTS * KNN);
            g_ticket = 0;  // reset for next graph replay
        }
    }
}

extern "C" void kernel_launch(void* const* d_in, const int* in_sizes, int n_in,
                              void* d_out, int out_size) {
    const float*  outputs = (const float*)d_in[0];
    const float2* points  = (const float2*)d_in[1];
    float* out = (float*)d_out;

    const int smem_bytes = NPTS * sizeof(float4) + NCELL * sizeof(int2);
    cudaFuncSetAttribute(search_kernel,
                         cudaFuncAttributeMaxDynamicSharedMemorySize,
                         smem_bytes);
    build_kernel<<<1, 1024>>>(points);
    search_kernel<<<SNBLK, STPB, smem_bytes>>>(outputs, out);
}